// round 3
// baseline (speedup 1.0000x reference)
#include <cuda_runtime.h>

#define N_NEURON 500000
#define N_EDGE   10000000

// dual-exponential constants (match reference exactly)
#define DT_C     0.1f
#define LAMDA_D  (0.1f / 2.0f)    // DT/TAO_D
#define LAMDA_R  (0.1f / 10.0f)   // DT/TAO_R
#define INV_TAO_D 0.5f            // 1/TAO_D

// scratch: r_new lives here between the two kernels (no cudaMalloc allowed)
__device__ float g_rnew[N_NEURON];

// ---------------------------------------------------------------------------
// Kernel A: per-neuron fused update, float4-vectorized (N_NEURON % 4 == 0).
//   Iback_new = Iback + dt_over_tau*(noise - Iback)
//   Ieff      = Iback_new / sqrt_coeff * sig + mu
//   s_new     = s + LAMDA_R*(-s + spike/TAO_D)
//   r_new     = r - LAMDA_D*r + DT*s_new
// Writes r_new to scratch, seeds out = Ieff (accumulator base).
// ---------------------------------------------------------------------------
__global__ void neuron_kernel(const float4* __restrict__ Iback,
                              const float4* __restrict__ spike,
                              const float4* __restrict__ s,
                              const float4* __restrict__ r,
                              const float4* __restrict__ noise,
                              const float* __restrict__ dt_over_tau,
                              const float* __restrict__ sqrt_coeff,
                              const float* __restrict__ sig,
                              const float* __restrict__ mu,
                              float4* __restrict__ out)
{
    int i = blockIdx.x * blockDim.x + threadIdx.x;
    if (i >= N_NEURON / 4) return;

    float dtau = __ldg(dt_over_tau);
    float scale = __ldg(sig) / __ldg(sqrt_coeff);
    float m    = __ldg(mu);

    float4 ib = Iback[i];
    float4 nz = noise[i];
    float4 sv = s[i];
    float4 sp = spike[i];
    float4 rv = r[i];

    float4 ieff, rn;
    {
        float ibn = ib.x + dtau * (nz.x - ib.x);
        ieff.x = ibn * scale + m;
        float sn = sv.x + LAMDA_R * (-sv.x + sp.x * INV_TAO_D);
        rn.x = rv.x - LAMDA_D * rv.x + DT_C * sn;
    }
    {
        float ibn = ib.y + dtau * (nz.y - ib.y);
        ieff.y = ibn * scale + m;
        float sn = sv.y + LAMDA_R * (-sv.y + sp.y * INV_TAO_D);
        rn.y = rv.y - LAMDA_D * rv.y + DT_C * sn;
    }
    {
        float ibn = ib.z + dtau * (nz.z - ib.z);
        ieff.z = ibn * scale + m;
        float sn = sv.z + LAMDA_R * (-sv.z + sp.z * INV_TAO_D);
        rn.z = rv.z - LAMDA_D * rv.z + DT_C * sn;
    }
    {
        float ibn = ib.w + dtau * (nz.w - ib.w);
        ieff.w = ibn * scale + m;
        float sn = sv.w + LAMDA_R * (-sv.w + sp.w * INV_TAO_D);
        rn.w = rv.w - LAMDA_D * rv.w + DT_C * sn;
    }

    reinterpret_cast<float4*>(g_rnew)[i] = rn;
    out[i] = ieff;   // accumulator base (out is poisoned by harness)
}

// ---------------------------------------------------------------------------
// Kernel B: COO edge scatter, 8 edges per thread, 128-bit loads.
//   out[post_e] += w_e * r_new[pre_e]
// edges are INT32 on device: post = edges[0:N_EDGE], pre = edges[N_EDGE:2N].
// All 8 gathers issued before any atomic (max L1tex queue occupancy);
// r_new (2 MB) and out (2 MB) are L2-resident; atomics compile to REDG.
// ---------------------------------------------------------------------------
__global__ void __launch_bounds__(256) edge_kernel(
                            const int* __restrict__ post,
                            const int* __restrict__ pre,
                            const float* __restrict__ w,
                            float* __restrict__ out)
{
    int t = blockIdx.x * blockDim.x + threadIdx.x;
    int i = t * 8;
    if (i >= N_EDGE) return;   // N_EDGE % 8 == 0, so full groups only

    int4   p0 = *reinterpret_cast<const int4*>(post + i);
    int4   p1 = *reinterpret_cast<const int4*>(post + i + 4);
    int4   q0 = *reinterpret_cast<const int4*>(pre + i);
    int4   q1 = *reinterpret_cast<const int4*>(pre + i + 4);
    float4 w0 = *reinterpret_cast<const float4*>(w + i);
    float4 w1 = *reinterpret_cast<const float4*>(w + i + 4);

    // gather all 8 first (maximize MLP), then scatter
    float r0 = __ldg(&g_rnew[q0.x]);
    float r1 = __ldg(&g_rnew[q0.y]);
    float r2 = __ldg(&g_rnew[q0.z]);
    float r3 = __ldg(&g_rnew[q0.w]);
    float r4 = __ldg(&g_rnew[q1.x]);
    float r5 = __ldg(&g_rnew[q1.y]);
    float r6 = __ldg(&g_rnew[q1.z]);
    float r7 = __ldg(&g_rnew[q1.w]);

    atomicAdd(out + p0.x, w0.x * r0);
    atomicAdd(out + p0.y, w0.y * r1);
    atomicAdd(out + p0.z, w0.z * r2);
    atomicAdd(out + p0.w, w0.w * r3);
    atomicAdd(out + p1.x, w1.x * r4);
    atomicAdd(out + p1.y, w1.y * r5);
    atomicAdd(out + p1.z, w1.z * r6);
    atomicAdd(out + p1.w, w1.w * r7);
}

extern "C" void kernel_launch(void* const* d_in, const int* in_sizes, int n_in,
                              void* d_out, int out_size)
{
    const float* weight      = (const float*)d_in[0];
    const int*   edges       = (const int*)d_in[1];   // [2, N_EDGE] int32
    const float* Iback       = (const float*)d_in[2];
    const float* spike       = (const float*)d_in[3];
    const float* s           = (const float*)d_in[4];
    const float* r           = (const float*)d_in[5];
    const float* noise       = (const float*)d_in[6];
    const float* dt_over_tau = (const float*)d_in[7];
    const float* sqrt_coeff  = (const float*)d_in[8];
    const float* sig         = (const float*)d_in[9];
    const float* mu          = (const float*)d_in[10];
    float* out = (float*)d_out;

    const int* post = edges;
    const int* pre  = edges + N_EDGE;

    // max-L1 carveout for the gather-heavy edge kernel (no smem used)
    static bool attr_set = false;
    if (!attr_set) {
        cudaFuncSetAttribute(edge_kernel,
                             cudaFuncAttributePreferredSharedMemoryCarveout, 0);
        attr_set = true;
    }

    int threads = 256;
    int nvec = N_NEURON / 4;
    int nblocks = (nvec + threads - 1) / threads;
    neuron_kernel<<<nblocks, threads>>>(
        (const float4*)Iback, (const float4*)spike, (const float4*)s,
        (const float4*)r, (const float4*)noise,
        dt_over_tau, sqrt_coeff, sig, mu, (float4*)out);

    int nthreads_edge = N_EDGE / 8;
    int eblocks = (nthreads_edge + threads - 1) / threads;
    edge_kernel<<<eblocks, threads>>>(post, pre, weight, out);
}

// round 5
// speedup vs baseline: 1.0576x; 1.0576x over previous
#include <cuda_runtime.h>

#define N_NEURON 500000
#define N_EDGE   10000000

// dual-exponential constants (match reference exactly)
#define DT_C     0.1f
#define LAMDA_D  (0.1f / 2.0f)    // DT/TAO_D
#define LAMDA_R  (0.1f / 10.0f)   // DT/TAO_R
#define INV_TAO_D 0.5f            // 1/TAO_D

// scratch: r_new lives here between the two kernels (no cudaMalloc allowed)
__device__ float g_rnew[N_NEURON];

// ---------------------------------------------------------------------------
// Kernel A: per-neuron fused update, float4-vectorized (N_NEURON % 4 == 0).
//   Iback_new = Iback + dt_over_tau*(noise - Iback)
//   Ieff      = Iback_new / sqrt_coeff * sig + mu
//   s_new     = s + LAMDA_R*(-s + spike/TAO_D)
//   r_new     = r - LAMDA_D*r + DT*s_new
// Writes r_new to scratch, seeds out = Ieff (accumulator base).
// ---------------------------------------------------------------------------
__global__ void neuron_kernel(const float4* __restrict__ Iback,
                              const float4* __restrict__ spike,
                              const float4* __restrict__ s,
                              const float4* __restrict__ r,
                              const float4* __restrict__ noise,
                              const float* __restrict__ dt_over_tau,
                              const float* __restrict__ sqrt_coeff,
                              const float* __restrict__ sig,
                              const float* __restrict__ mu,
                              float4* __restrict__ out)
{
    int i = blockIdx.x * blockDim.x + threadIdx.x;
    if (i >= N_NEURON / 4) return;

    float dtau  = __ldg(dt_over_tau);
    float scale = __ldg(sig) / __ldg(sqrt_coeff);
    float m     = __ldg(mu);

    float4 ib = Iback[i];
    float4 nz = noise[i];
    float4 sv = s[i];
    float4 sp = spike[i];
    float4 rv = r[i];

    float4 ieff, rn;
    {
        float ibn = ib.x + dtau * (nz.x - ib.x);
        ieff.x = ibn * scale + m;
        float sn = sv.x + LAMDA_R * (-sv.x + sp.x * INV_TAO_D);
        rn.x = rv.x - LAMDA_D * rv.x + DT_C * sn;
    }
    {
        float ibn = ib.y + dtau * (nz.y - ib.y);
        ieff.y = ibn * scale + m;
        float sn = sv.y + LAMDA_R * (-sv.y + sp.y * INV_TAO_D);
        rn.y = rv.y - LAMDA_D * rv.y + DT_C * sn;
    }
    {
        float ibn = ib.z + dtau * (nz.z - ib.z);
        ieff.z = ibn * scale + m;
        float sn = sv.z + LAMDA_R * (-sv.z + sp.z * INV_TAO_D);
        rn.z = rv.z - LAMDA_D * rv.z + DT_C * sn;
    }
    {
        float ibn = ib.w + dtau * (nz.w - ib.w);
        ieff.w = ibn * scale + m;
        float sn = sv.w + LAMDA_R * (-sv.w + sp.w * INV_TAO_D);
        rn.w = rv.w - LAMDA_D * rv.w + DT_C * sn;
    }

    reinterpret_cast<float4*>(g_rnew)[i] = rn;
    out[i] = ieff;   // accumulator base (out is poisoned by harness)
}

// ---------------------------------------------------------------------------
// Kernel B: COO edge scatter, 2 edges per thread (max thread-level
// parallelism to saturate LTS; kernel is L2-occupancy-bound).
//   out[post_e] += w_e * r_new[pre_e]
// edges are INT32 on device: post = edges[0:N_EDGE], pre = edges[N_EDGE:2N].
// Gathers issued before atomics; r_new (2 MB) and out (2 MB) are
// L2-resident; atomics compile to REDG.
// ---------------------------------------------------------------------------
__global__ void __launch_bounds__(256) edge_kernel(
                            const int* __restrict__ post,
                            const int* __restrict__ pre,
                            const float* __restrict__ w,
                            float* __restrict__ out)
{
    int t = blockIdx.x * blockDim.x + threadIdx.x;
    int i = t * 2;
    if (i >= N_EDGE) return;   // N_EDGE % 2 == 0, full pairs only

    int2   p  = *reinterpret_cast<const int2*>(post + i);
    int2   q  = *reinterpret_cast<const int2*>(pre + i);
    float2 ww = *reinterpret_cast<const float2*>(w + i);

    // gather first (overlap the two random loads), then scatter
    float r0 = __ldg(&g_rnew[q.x]);
    float r1 = __ldg(&g_rnew[q.y]);

    atomicAdd(out + p.x, ww.x * r0);
    atomicAdd(out + p.y, ww.y * r1);
}

extern "C" void kernel_launch(void* const* d_in, const int* in_sizes, int n_in,
                              void* d_out, int out_size)
{
    const float* weight      = (const float*)d_in[0];
    const int*   edges       = (const int*)d_in[1];   // [2, N_EDGE] int32
    const float* Iback       = (const float*)d_in[2];
    const float* spike       = (const float*)d_in[3];
    const float* s           = (const float*)d_in[4];
    const float* r           = (const float*)d_in[5];
    const float* noise       = (const float*)d_in[6];
    const float* dt_over_tau = (const float*)d_in[7];
    const float* sqrt_coeff  = (const float*)d_in[8];
    const float* sig         = (const float*)d_in[9];
    const float* mu          = (const float*)d_in[10];
    float* out = (float*)d_out;

    const int* post = edges;
    const int* pre  = edges + N_EDGE;

    int threads = 256;
    int nvec = N_NEURON / 4;
    int nblocks = (nvec + threads - 1) / threads;
    neuron_kernel<<<nblocks, threads>>>(
        (const float4*)Iback, (const float4*)spike, (const float4*)s,
        (const float4*)r, (const float4*)noise,
        dt_over_tau, sqrt_coeff, sig, mu, (float4*)out);

    int nthreads_edge = N_EDGE / 2;
    int eblocks = (nthreads_edge + threads - 1) / threads;
    edge_kernel<<<eblocks, threads>>>(post, pre, weight, out);
}